// round 1
// baseline (speedup 1.0000x reference)
#include <cuda_runtime.h>

// SE_loss_w_threshold: h,v (8,16384,128) fp32, N scalar.
// out (assumed 10 fp32): [mean_Rp, R_per_user[0..7], sum(R_per_user)]

#define NUSER 8
#define BATCH 16384
#define NT    128
#define ROWF  132                      // padded smem row stride (floats): 132 mod 32 = 4 -> conflict-free
#define WARP_TILE (2 * NUSER * ROWF)   // 2112 floats per warp (h + v tiles)
#define WPB   4                        // warps per block
#define THREADS (WPB * 32)
#define GRID  888                      // 148 SMs * 6 blocks/SM

__device__ double gAcc[9];             // [0]=sum_b Rp, [1..8]=sum_b R_user[i]

__global__ void se_zero_kernel() {
    if (threadIdx.x < 9) gAcc[threadIdx.x] = 0.0;
}

__global__ __launch_bounds__(THREADS)
void se_main_kernel(const float* __restrict__ hg,
                    const float* __restrict__ vg,
                    const float* __restrict__ Np)
{
    __shared__ float sh[WPB * WARP_TILE];

    const int lane = threadIdx.x & 31;
    const int wid  = threadIdx.x >> 5;
    const int gw   = blockIdx.x * WPB + wid;
    const int nw   = gridDim.x * WPB;

    float* sH = sh + wid * WARP_TILE;
    float* sV = sH + NUSER * ROWF;

    const float Nval = __ldg(Np);

    const int g  = lane >> 3;          // group 0..3
    const int j  = lane & 7;           // column of A this lane owns
    const int i1 = g;                  // row of A, pair 1
    const int i2 = g + 4;              // row of A, pair 2

    float accRp = 0.0f, accR1 = 0.0f, accR2 = 0.0f;

    for (int b = gw; b < BATCH; b += nw) {
        // ---- stage tiles to smem, compute ||v||^2 on the fly ----
        float nrm = 0.0f;
        #pragma unroll
        for (int u = 0; u < NUSER; u++) {
            const int base = (u * BATCH + b) << 7;   // *128
            const float4 hv = *(const float4*)(hg + base + (lane << 2));
            const float4 vv = *(const float4*)(vg + base + (lane << 2));
            *(float4*)(sH + u * ROWF + (lane << 2)) = hv;
            *(float4*)(sV + u * ROWF + (lane << 2)) = vv;
            nrm = fmaf(vv.x, vv.x, fmaf(vv.y, vv.y,
                  fmaf(vv.z, vv.z, fmaf(vv.w, vv.w, nrm))));
        }
        #pragma unroll
        for (int o = 16; o; o >>= 1)
            nrm += __shfl_xor_sync(0xffffffffu, nrm, o);
        __syncwarp();

        // ---- complex dots: A(i1,j), A(i2,j), each over d=64 ----
        const float* h1 = sH + i1 * ROWF;
        const float* h2 = sH + i2 * ROWF;
        const float* vv = sV + j  * ROWF;

        float re1 = 0.f, re1b = 0.f, im1 = 0.f, im1b = 0.f;
        float re2 = 0.f, re2b = 0.f, im2 = 0.f, im2b = 0.f;

        #pragma unroll
        for (int c = 0; c < 16; c++) {
            const float4 vlo = *(const float4*)(vv + 4 * c);
            const float4 vhi = *(const float4*)(vv + 64 + 4 * c);
            const float4 alo = *(const float4*)(h1 + 4 * c);
            const float4 ahi = *(const float4*)(h1 + 64 + 4 * c);
            const float4 blo = *(const float4*)(h2 + 4 * c);
            const float4 bhi = *(const float4*)(h2 + 64 + 4 * c);

            // re = hr.vr + hi.vi ; im = hi.vr - hr.vi
            re1  = fmaf(alo.x, vlo.x, fmaf(alo.y, vlo.y, re1));
            re1b = fmaf(alo.z, vlo.z, fmaf(alo.w, vlo.w, re1b));
            re1  = fmaf(ahi.x, vhi.x, fmaf(ahi.y, vhi.y, re1));
            re1b = fmaf(ahi.z, vhi.z, fmaf(ahi.w, vhi.w, re1b));
            im1  = fmaf(ahi.x, vlo.x, fmaf(ahi.y, vlo.y, im1));
            im1b = fmaf(ahi.z, vlo.z, fmaf(ahi.w, vlo.w, im1b));
            im1  = fmaf(-alo.x, vhi.x, fmaf(-alo.y, vhi.y, im1));
            im1b = fmaf(-alo.z, vhi.z, fmaf(-alo.w, vhi.w, im1b));

            re2  = fmaf(blo.x, vlo.x, fmaf(blo.y, vlo.y, re2));
            re2b = fmaf(blo.z, vlo.z, fmaf(blo.w, vlo.w, re2b));
            re2  = fmaf(bhi.x, vhi.x, fmaf(bhi.y, vhi.y, re2));
            re2b = fmaf(bhi.z, vhi.z, fmaf(bhi.w, vhi.w, re2b));
            im2  = fmaf(bhi.x, vlo.x, fmaf(bhi.y, vlo.y, im2));
            im2b = fmaf(bhi.z, vlo.z, fmaf(bhi.w, vlo.w, im2b));
            im2  = fmaf(-blo.x, vhi.x, fmaf(-blo.y, vhi.y, im2));
            im2b = fmaf(-blo.z, vhi.z, fmaf(-blo.w, vhi.w, im2b));
        }

        const float A1r = re1 + re1b, A1i = im1 + im1b;
        const float A2r = re2 + re2b, A2i = im2 + im2b;
        float p1 = fmaf(A1r, A1r, A1i * A1i);   // |A(i1,j)|^2
        float p2 = fmaf(A2r, A2r, A2i * A2i);   // |A(i2,j)|^2

        // sum over j within the 8-lane group
        float s1 = p1, s2 = p2;
        #pragma unroll
        for (int o = 1; o < 8; o <<= 1) {
            s1 += __shfl_xor_sync(0xffffffffu, s1, o);
            s2 += __shfl_xor_sync(0xffffffffu, s2, o);
        }
        // diagonals |A(i,i)|^2 (variable-source shuffles within group)
        const float d1 = __shfl_sync(0xffffffffu, p1, g * 9);       // lane 8g+g
        const float d2 = __shfl_sync(0xffffffffu, p2, g * 8 + g + 4);

        if (j == 0) {
            const float scale2 = 8.0f / nrm;    // NUM_USER / ||v||^2
            const float S1 = d1 * scale2;
            const float S2 = d2 * scale2;
            const float sinr1 = S1 / (s1 - d1 + Nval);
            const float sinr2 = S2 / (s2 - d2 + Nval);
            const float R1 = log2f(1.0f + sinr1);
            const float R2 = log2f(1.0f + sinr2);
            accR1 += R1;
            accR2 += R2;
            const float L10 = 3.3219280948873623f; // log2(10)
            accRp += exp2f((0.3f - R1) * L10) - R1
                   + exp2f((0.3f - R2) * L10) - R2;
        }
        __syncwarp();   // protect smem before next iteration's staging
    }

    if (j == 0) {
        atomicAdd(&gAcc[0],      (double)accRp);
        atomicAdd(&gAcc[1 + i1], (double)accR1);
        atomicAdd(&gAcc[1 + i2], (double)accR2);
    }
}

__global__ void se_finalize_kernel(float* __restrict__ out, int out_size) {
    if (threadIdx.x == 0) {
        const double inv = 1.0 / (double)BATCH;
        double s = 0.0;
        float r[8];
        #pragma unroll
        for (int i = 0; i < 8; i++) {
            double m = gAcc[1 + i] * inv;
            r[i] = (float)m;
            s += m;
        }
        if (out_size >= 1) out[0] = (float)(gAcc[0] * inv);
        if (out_size >= 10) {
            #pragma unroll
            for (int i = 0; i < 8; i++) out[1 + i] = r[i];
            out[9] = (float)s;
        }
    }
}

extern "C" void kernel_launch(void* const* d_in, const int* in_sizes, int n_in,
                              void* d_out, int out_size)
{
    const float* h = (const float*)d_in[0];
    const float* v = (const float*)d_in[1];
    const float* N = (const float*)d_in[2];
    float* out = (float*)d_out;

    se_zero_kernel<<<1, 32>>>();
    se_main_kernel<<<GRID, THREADS>>>(h, v, N);
    se_finalize_kernel<<<1, 32>>>(out, out_size);
}

// round 2
// speedup vs baseline: 1.3472x; 1.3472x over previous
#include <cuda_runtime.h>

// SE_loss_w_threshold: h,v (8,16384,128) fp32, N scalar.
// out (10 fp32): [mean_Rp, R_per_user[0..7], sum(R_per_user)]
// Single fused persistent kernel: compute + global reduction + finalize.

#define NUSER 8
#define BATCH 16384
#define ROWF  132                      // padded smem row stride (floats); conflict-free
#define WARP_TILE (2 * NUSER * ROWF)   // h + v tiles per warp
#define WPB   4
#define THREADS (WPB * 32)
#define GRID  512                      // 2048 warps * 8 batches = 16384 exactly

typedef unsigned long long u64;

__device__ double gAcc[9];             // zero at module load; reset by last block each call
__device__ unsigned int gCount = 0;    // wraps back to 0 via atomicInc

__device__ __forceinline__ u64 ffma2(u64 a, u64 b, u64 c) {
    u64 d;
    asm("fma.rn.f32x2 %0, %1, %2, %3;" : "=l"(d) : "l"(a), "l"(b), "l"(c));
    return d;
}
__device__ __forceinline__ u64 packf2(float x, float y) {
    u64 d;
    asm("mov.b64 %0, {%1, %2};" : "=l"(d) : "f"(x), "f"(y));
    return d;
}
__device__ __forceinline__ float2 unpackf2(u64 a) {
    float2 f;
    asm("mov.b64 {%0, %1}, %2;" : "=f"(f.x), "=f"(f.y) : "l"(a));
    return f;
}
__device__ __forceinline__ float hsum2(u64 a) {
    float2 f = unpackf2(a);
    return f.x + f.y;
}

__global__ __launch_bounds__(THREADS)
void se_fused_kernel(const float* __restrict__ hg,
                     const float* __restrict__ vg,
                     const float* __restrict__ Np,
                     float* __restrict__ out, int out_size)
{
    __shared__ float sh[WPB * WARP_TILE];
    __shared__ double sAcc[9];
    __shared__ int sLast;

    const int tid  = threadIdx.x;
    const int lane = tid & 31;
    const int wid  = tid >> 5;

    if (tid < 9) sAcc[tid] = 0.0;
    __syncthreads();

    const int gw = blockIdx.x * WPB + wid;
    const int nw = GRID * WPB;

    float* sH = sh + wid * WARP_TILE;
    float* sV = sH + NUSER * ROWF;

    const float Nval = __ldg(Np);

    const int g  = lane >> 3;          // group 0..3
    const int j  = lane & 7;           // column of A
    const int i1 = g;
    const int i2 = g + 4;

    float accRp = 0.0f, accR1 = 0.0f, accR2 = 0.0f;

    for (int b = gw; b < BATCH; b += nw) {
        // ---- stage tiles, compute ||v||^2 (packed) ----
        u64 nrm2 = 0ULL;
        #pragma unroll
        for (int u = 0; u < NUSER; u++) {
            const int base = (u * BATCH + b) << 7;
            const float4 hv = *(const float4*)(hg + base + (lane << 2));
            const float4 vv = *(const float4*)(vg + base + (lane << 2));
            *(float4*)(sH + u * ROWF + (lane << 2)) = hv;
            *(float4*)(sV + u * ROWF + (lane << 2)) = vv;
            const u64 p0 = packf2(vv.x, vv.y);
            const u64 p1 = packf2(vv.z, vv.w);
            nrm2 = ffma2(p0, p0, nrm2);
            nrm2 = ffma2(p1, p1, nrm2);
        }
        float nrm = hsum2(nrm2);
        #pragma unroll
        for (int o = 16; o; o >>= 1)
            nrm += __shfl_xor_sync(0xffffffffu, nrm, o);
        __syncwarp();

        // ---- complex dots A(i1,j), A(i2,j) over d=64, packed f32x2 ----
        const ulonglong2* h1p = (const ulonglong2*)(sH + i1 * ROWF);
        const ulonglong2* h2p = (const ulonglong2*)(sH + i2 * ROWF);
        const ulonglong2* vvp = (const ulonglong2*)(sV + j  * ROWF);

        u64 re1 = 0, re1b = 0, ip1 = 0, ip1b = 0, in1 = 0, in1b = 0;
        u64 re2 = 0, re2b = 0, ip2 = 0, ip2b = 0, in2 = 0, in2b = 0;

        #pragma unroll
        for (int c = 0; c < 16; c++) {
            const ulonglong2 vlo = vvp[c];
            const ulonglong2 vhi = vvp[16 + c];
            const ulonglong2 alo = h1p[c];
            const ulonglong2 ahi = h1p[16 + c];
            const ulonglong2 blo = h2p[c];
            const ulonglong2 bhi = h2p[16 + c];

            // re = hr.vr + hi.vi ; im = (hi.vr) - (hr.vi) split pos/neg
            re1  = ffma2(alo.x, vlo.x, re1);   re1b = ffma2(alo.y, vlo.y, re1b);
            re1  = ffma2(ahi.x, vhi.x, re1);   re1b = ffma2(ahi.y, vhi.y, re1b);
            ip1  = ffma2(ahi.x, vlo.x, ip1);   ip1b = ffma2(ahi.y, vlo.y, ip1b);
            in1  = ffma2(alo.x, vhi.x, in1);   in1b = ffma2(alo.y, vhi.y, in1b);

            re2  = ffma2(blo.x, vlo.x, re2);   re2b = ffma2(blo.y, vlo.y, re2b);
            re2  = ffma2(bhi.x, vhi.x, re2);   re2b = ffma2(bhi.y, vhi.y, re2b);
            ip2  = ffma2(bhi.x, vlo.x, ip2);   ip2b = ffma2(bhi.y, vlo.y, ip2b);
            in2  = ffma2(blo.x, vhi.x, in2);   in2b = ffma2(blo.y, vhi.y, in2b);
        }

        const float A1r = hsum2(re1) + hsum2(re1b);
        const float A1i = (hsum2(ip1) + hsum2(ip1b)) - (hsum2(in1) + hsum2(in1b));
        const float A2r = hsum2(re2) + hsum2(re2b);
        const float A2i = (hsum2(ip2) + hsum2(ip2b)) - (hsum2(in2) + hsum2(in2b));

        float p1 = fmaf(A1r, A1r, A1i * A1i);
        float p2 = fmaf(A2r, A2r, A2i * A2i);

        // sum over j within 8-lane group
        float s1 = p1, s2 = p2;
        #pragma unroll
        for (int o = 1; o < 8; o <<= 1) {
            s1 += __shfl_xor_sync(0xffffffffu, s1, o);
            s2 += __shfl_xor_sync(0xffffffffu, s2, o);
        }
        // diagonal terms |A(i,i)|^2
        const float d1 = __shfl_sync(0xffffffffu, p1, g * 9);           // lane 8g+g
        const float d2 = __shfl_sync(0xffffffffu, p2, g * 8 + g + 4);   // lane 8g+(g+4)

        if (j == 0) {
            const float scale2 = 8.0f / nrm;
            const float sinr1 = __fdividef(d1 * scale2, s1 - d1 + Nval);
            const float sinr2 = __fdividef(d2 * scale2, s2 - d2 + Nval);
            const float R1 = __log2f(1.0f + sinr1);
            const float R2 = __log2f(1.0f + sinr2);
            accR1 += R1;
            accR2 += R2;
            accRp += __exp10f(0.3f - R1) - R1
                   + __exp10f(0.3f - R2) - R2;
        }
        __syncwarp();
    }

    // ---- block-level reduction into shared doubles ----
    if (j == 0) {
        atomicAdd(&sAcc[0],      (double)accRp);
        atomicAdd(&sAcc[1 + i1], (double)accR1);
        atomicAdd(&sAcc[1 + i2], (double)accR2);
    }
    __syncthreads();

    if (tid < 9) atomicAdd(&gAcc[tid], sAcc[tid]);
    __threadfence();
    __syncthreads();

    if (tid == 0) {
        const unsigned old = atomicInc(&gCount, GRID - 1); // wraps to 0 after GRID incs
        sLast = (old == GRID - 1) ? 1 : 0;
    }
    __syncthreads();

    if (sLast && tid == 0) {
        __threadfence();
        const double inv = 1.0 / (double)BATCH;
        double r[9];
        #pragma unroll
        for (int i = 0; i < 9; i++) {
            r[i] = __ldcg(&gAcc[i]);
            __stcg(&gAcc[i], 0.0);     // reset for next graph replay
        }
        double s = 0.0;
        #pragma unroll
        for (int i = 1; i < 9; i++) s += r[i] * inv;
        if (out_size >= 1) out[0] = (float)(r[0] * inv);
        if (out_size >= 10) {
            #pragma unroll
            for (int i = 0; i < 8; i++) out[1 + i] = (float)(r[1 + i] * inv);
            out[9] = (float)s;
        }
    }
}

extern "C" void kernel_launch(void* const* d_in, const int* in_sizes, int n_in,
                              void* d_out, int out_size)
{
    const float* h = (const float*)d_in[0];
    const float* v = (const float*)d_in[1];
    const float* N = (const float*)d_in[2];
    float* out = (float*)d_out;

    se_fused_kernel<<<GRID, THREADS>>>(h, v, N, out, out_size);
}

// round 3
// speedup vs baseline: 1.5877x; 1.1785x over previous
#include <cuda_runtime.h>

// SE_loss_w_threshold: h,v (8,16384,128) fp32, N scalar.
// out (10 fp32): [mean_Rp, R_per_user[0..7], sum(R_per_user)]
// Single fused persistent kernel: compute + global reduction + finalize.
// R3: GRID=888 (6 blocks/SM resident, matches reg+smem occupancy limit).

#define NUSER 8
#define BATCH 16384
#define ROWF  132                      // padded smem row stride (floats); conflict-free
#define WARP_TILE (2 * NUSER * ROWF)   // h + v tiles per warp
#define WPB   4
#define THREADS (WPB * 32)
#define GRID  888                      // 148 SMs * 6 blocks/SM, single wave

typedef unsigned long long u64;

__device__ double gAcc[9];             // zero at module load; reset by last block each call
__device__ unsigned int gCount = 0;    // wraps back to 0 via atomicInc

__device__ __forceinline__ u64 ffma2(u64 a, u64 b, u64 c) {
    u64 d;
    asm("fma.rn.f32x2 %0, %1, %2, %3;" : "=l"(d) : "l"(a), "l"(b), "l"(c));
    return d;
}
__device__ __forceinline__ u64 packf2(float x, float y) {
    u64 d;
    asm("mov.b64 %0, {%1, %2};" : "=l"(d) : "f"(x), "f"(y));
    return d;
}
__device__ __forceinline__ float2 unpackf2(u64 a) {
    float2 f;
    asm("mov.b64 {%0, %1}, %2;" : "=f"(f.x), "=f"(f.y) : "l"(a));
    return f;
}
__device__ __forceinline__ float hsum2(u64 a) {
    float2 f = unpackf2(a);
    return f.x + f.y;
}

__global__ __launch_bounds__(THREADS)
void se_fused_kernel(const float* __restrict__ hg,
                     const float* __restrict__ vg,
                     const float* __restrict__ Np,
                     float* __restrict__ out, int out_size)
{
    __shared__ float sh[WPB * WARP_TILE];
    __shared__ double sAcc[9];
    __shared__ int sLast;

    const int tid  = threadIdx.x;
    const int lane = tid & 31;
    const int wid  = tid >> 5;

    if (tid < 9) sAcc[tid] = 0.0;
    __syncthreads();

    const int gw = blockIdx.x * WPB + wid;
    const int nw = GRID * WPB;

    float* sH = sh + wid * WARP_TILE;
    float* sV = sH + NUSER * ROWF;

    const float Nval = __ldg(Np);

    const int g  = lane >> 3;          // group 0..3
    const int j  = lane & 7;           // column of A
    const int i1 = g;
    const int i2 = g + 4;

    float accRp = 0.0f, accR1 = 0.0f, accR2 = 0.0f;

    for (int b = gw; b < BATCH; b += nw) {
        // ---- stage tiles, compute ||v||^2 (packed) ----
        u64 nrm2 = 0ULL;
        #pragma unroll
        for (int u = 0; u < NUSER; u++) {
            const int base = (u * BATCH + b) << 7;
            const float4 hv = *(const float4*)(hg + base + (lane << 2));
            const float4 vv = *(const float4*)(vg + base + (lane << 2));
            *(float4*)(sH + u * ROWF + (lane << 2)) = hv;
            *(float4*)(sV + u * ROWF + (lane << 2)) = vv;
            const u64 p0 = packf2(vv.x, vv.y);
            const u64 p1 = packf2(vv.z, vv.w);
            nrm2 = ffma2(p0, p0, nrm2);
            nrm2 = ffma2(p1, p1, nrm2);
        }
        float nrm = hsum2(nrm2);
        #pragma unroll
        for (int o = 16; o; o >>= 1)
            nrm += __shfl_xor_sync(0xffffffffu, nrm, o);
        __syncwarp();

        // ---- complex dots A(i1,j), A(i2,j) over d=64, packed f32x2 ----
        const ulonglong2* h1p = (const ulonglong2*)(sH + i1 * ROWF);
        const ulonglong2* h2p = (const ulonglong2*)(sH + i2 * ROWF);
        const ulonglong2* vvp = (const ulonglong2*)(sV + j  * ROWF);

        u64 re1 = 0, re1b = 0, ip1 = 0, ip1b = 0, in1 = 0, in1b = 0;
        u64 re2 = 0, re2b = 0, ip2 = 0, ip2b = 0, in2 = 0, in2b = 0;

        #pragma unroll
        for (int c = 0; c < 16; c++) {
            const ulonglong2 vlo = vvp[c];
            const ulonglong2 vhi = vvp[16 + c];
            const ulonglong2 alo = h1p[c];
            const ulonglong2 ahi = h1p[16 + c];
            const ulonglong2 blo = h2p[c];
            const ulonglong2 bhi = h2p[16 + c];

            // re = hr.vr + hi.vi ; im = (hi.vr) - (hr.vi) split pos/neg
            re1  = ffma2(alo.x, vlo.x, re1);   re1b = ffma2(alo.y, vlo.y, re1b);
            re1  = ffma2(ahi.x, vhi.x, re1);   re1b = ffma2(ahi.y, vhi.y, re1b);
            ip1  = ffma2(ahi.x, vlo.x, ip1);   ip1b = ffma2(ahi.y, vlo.y, ip1b);
            in1  = ffma2(alo.x, vhi.x, in1);   in1b = ffma2(alo.y, vhi.y, in1b);

            re2  = ffma2(blo.x, vlo.x, re2);   re2b = ffma2(blo.y, vlo.y, re2b);
            re2  = ffma2(bhi.x, vhi.x, re2);   re2b = ffma2(bhi.y, vhi.y, re2b);
            ip2  = ffma2(bhi.x, vlo.x, ip2);   ip2b = ffma2(bhi.y, vlo.y, ip2b);
            in2  = ffma2(blo.x, vhi.x, in2);   in2b = ffma2(blo.y, vhi.y, in2b);
        }

        const float A1r = hsum2(re1) + hsum2(re1b);
        const float A1i = (hsum2(ip1) + hsum2(ip1b)) - (hsum2(in1) + hsum2(in1b));
        const float A2r = hsum2(re2) + hsum2(re2b);
        const float A2i = (hsum2(ip2) + hsum2(ip2b)) - (hsum2(in2) + hsum2(in2b));

        float p1 = fmaf(A1r, A1r, A1i * A1i);
        float p2 = fmaf(A2r, A2r, A2i * A2i);

        // sum over j within 8-lane group
        float s1 = p1, s2 = p2;
        #pragma unroll
        for (int o = 1; o < 8; o <<= 1) {
            s1 += __shfl_xor_sync(0xffffffffu, s1, o);
            s2 += __shfl_xor_sync(0xffffffffu, s2, o);
        }
        // diagonal terms |A(i,i)|^2
        const float d1 = __shfl_sync(0xffffffffu, p1, g * 9);           // lane 8g+g
        const float d2 = __shfl_sync(0xffffffffu, p2, g * 8 + g + 4);   // lane 8g+(g+4)

        if (j == 0) {
            const float scale2 = 8.0f / nrm;
            const float sinr1 = __fdividef(d1 * scale2, s1 - d1 + Nval);
            const float sinr2 = __fdividef(d2 * scale2, s2 - d2 + Nval);
            const float R1 = __log2f(1.0f + sinr1);
            const float R2 = __log2f(1.0f + sinr2);
            accR1 += R1;
            accR2 += R2;
            accRp += __exp10f(0.3f - R1) - R1
                   + __exp10f(0.3f - R2) - R2;
        }
        __syncwarp();
    }

    // ---- block-level reduction into shared doubles ----
    if (j == 0) {
        atomicAdd(&sAcc[0],      (double)accRp);
        atomicAdd(&sAcc[1 + i1], (double)accR1);
        atomicAdd(&sAcc[1 + i2], (double)accR2);
    }
    __syncthreads();

    if (tid < 9) atomicAdd(&gAcc[tid], sAcc[tid]);
    __threadfence();
    __syncthreads();

    if (tid == 0) {
        const unsigned old = atomicInc(&gCount, GRID - 1); // wraps to 0 after GRID incs
        sLast = (old == GRID - 1) ? 1 : 0;
    }
    __syncthreads();

    if (sLast && tid == 0) {
        __threadfence();
        const double inv = 1.0 / (double)BATCH;
        double r[9];
        #pragma unroll
        for (int i = 0; i < 9; i++) {
            r[i] = __ldcg(&gAcc[i]);
            __stcg(&gAcc[i], 0.0);     // reset for next graph replay
        }
        double s = 0.0;
        #pragma unroll
        for (int i = 1; i < 9; i++) s += r[i] * inv;
        if (out_size >= 1) out[0] = (float)(r[0] * inv);
        if (out_size >= 10) {
            #pragma unroll
            for (int i = 0; i < 8; i++) out[1 + i] = (float)(r[1 + i] * inv);
            out[9] = (float)s;
        }
    }
}

extern "C" void kernel_launch(void* const* d_in, const int* in_sizes, int n_in,
                              void* d_out, int out_size)
{
    const float* h = (const float*)d_in[0];
    const float* v = (const float*)d_in[1];
    const float* N = (const float*)d_in[2];
    float* out = (float*)d_out;

    se_fused_kernel<<<GRID, THREADS>>>(h, v, N, out, out_size);
}

// round 4
// speedup vs baseline: 1.6367x; 1.0308x over previous
#include <cuda_runtime.h>

// SE_loss_w_threshold: h,v (8,16384,128) fp32, N scalar.
// out (10 fp32): [mean_Rp, R_per_user[0..7], sum(R_per_user)]
// R4: 2x2xK-split lane blocking -> LDS instrs 96->64/batch, each 1 crossbar
// cycle (128B distinct) instead of 4. Same smem/occupancy as R3.

#define NUSER 8
#define BATCH 16384
#define ROWF  132                      // 132 mod 16 = 4 -> rows 2c land on banks 8c
#define TILE  (NUSER * ROWF)
#define WARP_TILE (2 * TILE)           // h tile + v tile
#define WPB   4
#define THREADS (WPB * 32)
#define GRID  888                      // 148 SMs * 6 blocks/SM, single wave

typedef unsigned long long u64;

__device__ double gAcc[9];
__device__ unsigned int gCount = 0;

__device__ __forceinline__ u64 ffma2(u64 a, u64 b, u64 c) {
    u64 d;
    asm("fma.rn.f32x2 %0, %1, %2, %3;" : "=l"(d) : "l"(a), "l"(b), "l"(c));
    return d;
}
__device__ __forceinline__ float hsum2(u64 a) {
    float2 f;
    asm("mov.b64 {%0, %1}, %2;" : "=f"(f.x), "=f"(f.y) : "l"(a));
    return f.x + f.y;
}

// complex-dot partial update for one (h,v) pair over 4 t-values (2 f32x2 lo + 2 hi)
#define DOT(re, ip, in, hl, hh, vl, vh)            \
    re = ffma2((hl).x, (vl).x, re);                \
    re = ffma2((hl).y, (vl).y, re);                \
    re = ffma2((hh).x, (vh).x, re);                \
    re = ffma2((hh).y, (vh).y, re);                \
    ip = ffma2((hh).x, (vl).x, ip);                \
    ip = ffma2((hh).y, (vl).y, ip);                \
    in = ffma2((hl).x, (vh).x, in);                \
    in = ffma2((hl).y, (vh).y, in);

__global__ __launch_bounds__(THREADS)
void se_fused_kernel(const float* __restrict__ hg,
                     const float* __restrict__ vg,
                     const float* __restrict__ Np,
                     float* __restrict__ out, int out_size)
{
    __shared__ __align__(16) float sh[WPB * WARP_TILE];
    __shared__ double sAcc[9];
    __shared__ int sLast;

    const int tid  = threadIdx.x;
    const int lane = tid & 31;
    const int wid  = tid >> 5;

    if (tid < 9) sAcc[tid] = 0.0;
    __syncthreads();

    const int gw = blockIdx.x * WPB + wid;
    const int nw = GRID * WPB;

    float* sH = sh + wid * WARP_TILE;
    float* sV = sH + TILE;

    const float Nval = __ldg(Np);

    // lane decomposition: c = cols bit, a = rows, k2 = t-split
    const int c  = lane & 3;
    const int a  = (lane >> 2) & 3;
    const int k2 = lane >> 4;

    const float* hr0 = sH + (2 * a) * ROWF;
    const float* hr1 = hr0 + ROWF;
    const float* vc0 = sV + (2 * c) * ROWF;
    const float* vc1 = vc0 + ROWF;
    const int t0 = k2 * 4;             // float offset of this lane's first 16B block

    float accRp = 0.0f, accR0 = 0.0f, accR1 = 0.0f;

    for (int b = gw; b < BATCH; b += nw) {
        // ---- stage h,v tiles (coalesced), compute ||v||^2 ----
        u64 nrm2 = 0ULL;
        #pragma unroll
        for (int u = 0; u < NUSER; u++) {
            const int base4 = (u * BATCH + b) * 32 + lane;   // float4 index
            const ulonglong2 hv = *((const ulonglong2*)hg + base4);
            const ulonglong2 vv = *((const ulonglong2*)vg + base4);
            *(ulonglong2*)(sH + u * ROWF + (lane << 2)) = hv;
            *(ulonglong2*)(sV + u * ROWF + (lane << 2)) = vv;
            nrm2 = ffma2(vv.x, vv.x, nrm2);
            nrm2 = ffma2(vv.y, vv.y, nrm2);
        }
        float nrm = hsum2(nrm2);
        #pragma unroll
        for (int o = 16; o; o >>= 1)
            nrm += __shfl_xor_sync(0xffffffffu, nrm, o);
        __syncwarp();

        // ---- 2x2 block of complex dots over this lane's t-half ----
        u64 re00 = 0, ip00 = 0, in00 = 0;
        u64 re01 = 0, ip01 = 0, in01 = 0;
        u64 re10 = 0, ip10 = 0, in10 = 0;
        u64 re11 = 0, ip11 = 0, in11 = 0;

        #pragma unroll
        for (int m = 0; m < 8; m++) {
            const int off = t0 + m * 8;    // interleaved 16B blocks per k2
            const ulonglong2 h0l = *(const ulonglong2*)(hr0 + off);
            const ulonglong2 h0h = *(const ulonglong2*)(hr0 + off + 64);
            const ulonglong2 h1l = *(const ulonglong2*)(hr1 + off);
            const ulonglong2 h1h = *(const ulonglong2*)(hr1 + off + 64);
            const ulonglong2 v0l = *(const ulonglong2*)(vc0 + off);
            const ulonglong2 v0h = *(const ulonglong2*)(vc0 + off + 64);
            const ulonglong2 v1l = *(const ulonglong2*)(vc1 + off);
            const ulonglong2 v1h = *(const ulonglong2*)(vc1 + off + 64);

            DOT(re00, ip00, in00, h0l, h0h, v0l, v0h)
            DOT(re01, ip01, in01, h0l, h0h, v1l, v1h)
            DOT(re10, ip10, in10, h1l, h1h, v0l, v0h)
            DOT(re11, ip11, in11, h1l, h1h, v1l, v1h)
        }

        // collapse f32x2 partials
        float Ar00 = hsum2(re00), Ai00 = hsum2(ip00) - hsum2(in00);
        float Ar01 = hsum2(re01), Ai01 = hsum2(ip01) - hsum2(in01);
        float Ar10 = hsum2(re10), Ai10 = hsum2(ip10) - hsum2(in10);
        float Ar11 = hsum2(re11), Ai11 = hsum2(ip11) - hsum2(in11);

        // combine the two k2 halves
        Ar00 += __shfl_xor_sync(0xffffffffu, Ar00, 16);
        Ai00 += __shfl_xor_sync(0xffffffffu, Ai00, 16);
        Ar01 += __shfl_xor_sync(0xffffffffu, Ar01, 16);
        Ai01 += __shfl_xor_sync(0xffffffffu, Ai01, 16);
        Ar10 += __shfl_xor_sync(0xffffffffu, Ar10, 16);
        Ai10 += __shfl_xor_sync(0xffffffffu, Ai10, 16);
        Ar11 += __shfl_xor_sync(0xffffffffu, Ar11, 16);
        Ai11 += __shfl_xor_sync(0xffffffffu, Ai11, 16);

        const float p00 = fmaf(Ar00, Ar00, Ai00 * Ai00);
        const float p01 = fmaf(Ar01, Ar01, Ai01 * Ai01);
        const float p10 = fmaf(Ar10, Ar10, Ai10 * Ai10);
        const float p11 = fmaf(Ar11, Ar11, Ai11 * Ai11);

        // diagonals live in lane c==a: p00 -> (2a,2a), p11 -> (2a+1,2a+1)
        const float d0 = p00, d1 = p11;

        // row sums over all 8 columns (reduce across c bits 0,1)
        float s0 = p00 + p01;
        float s1 = p10 + p11;
        s0 += __shfl_xor_sync(0xffffffffu, s0, 1);
        s1 += __shfl_xor_sync(0xffffffffu, s1, 1);
        s0 += __shfl_xor_sync(0xffffffffu, s0, 2);
        s1 += __shfl_xor_sync(0xffffffffu, s1, 2);

        if (c == a && k2 == 0) {
            const float scale2 = 8.0f / nrm;
            const float sinr0 = __fdividef(d0 * scale2, s0 - d0 + Nval);
            const float sinr1 = __fdividef(d1 * scale2, s1 - d1 + Nval);
            const float R0 = __log2f(1.0f + sinr0);
            const float R1 = __log2f(1.0f + sinr1);
            accR0 += R0;
            accR1 += R1;
            accRp += __exp10f(0.3f - R0) - R0
                   + __exp10f(0.3f - R1) - R1;
        }
        __syncwarp();   // protect smem before next staging
    }

    // ---- block-level reduction ----
    if (c == a && k2 == 0) {
        atomicAdd(&sAcc[0],         (double)accRp);
        atomicAdd(&sAcc[1 + 2 * a], (double)accR0);
        atomicAdd(&sAcc[2 + 2 * a], (double)accR1);
    }
    __syncthreads();

    if (tid < 9) atomicAdd(&gAcc[tid], sAcc[tid]);
    __threadfence();
    __syncthreads();

    if (tid == 0) {
        const unsigned old = atomicInc(&gCount, GRID - 1);
        sLast = (old == GRID - 1) ? 1 : 0;
    }
    __syncthreads();

    if (sLast && tid == 0) {
        __threadfence();
        const double inv = 1.0 / (double)BATCH;
        double r[9];
        #pragma unroll
        for (int i = 0; i < 9; i++) {
            r[i] = __ldcg(&gAcc[i]);
            __stcg(&gAcc[i], 0.0);
        }
        double s = 0.0;
        #pragma unroll
        for (int i = 1; i < 9; i++) s += r[i] * inv;
        if (out_size >= 1) out[0] = (float)(r[0] * inv);
        if (out_size >= 10) {
            #pragma unroll
            for (int i = 0; i < 8; i++) out[1 + i] = (float)(r[1 + i] * inv);
            out[9] = (float)s;
        }
    }
}

extern "C" void kernel_launch(void* const* d_in, const int* in_sizes, int n_in,
                              void* d_out, int out_size)
{
    const float* h = (const float*)d_in[0];
    const float* v = (const float*)d_in[1];
    const float* N = (const float*)d_in[2];
    float* out = (float*)d_out;

    se_fused_kernel<<<GRID, THREADS>>>(h, v, N, out, out_size);
}

// round 5
// speedup vs baseline: 1.7971x; 1.0980x over previous
#include <cuda_runtime.h>

// SE_loss_w_threshold: h,v (8,16384,128) fp32, N scalar.
// out (10 fp32): [mean_Rp, R_per_user[0..7], sum(R_per_user)]
// R5: cp.async prefetch pipeline (next batch's loads overlap reductions +
// scalar tail) + 8 blocks/SM via launch_bounds (regs<=64), GRID=1184.

#define NUSER 8
#define BATCH 16384
#define ROWF  132                      // padded row stride (floats), conflict-free
#define TILE  (NUSER * ROWF)
#define WARP_TILE (2 * TILE)           // h tile + v tile
#define WPB   4
#define THREADS (WPB * 32)
#define GRID  1184                     // 148 SMs * 8 blocks/SM, single wave

typedef unsigned long long u64;

__device__ double gAcc[9];
__device__ unsigned int gCount = 0;

__device__ __forceinline__ u64 ffma2(u64 a, u64 b, u64 c) {
    u64 d;
    asm("fma.rn.f32x2 %0, %1, %2, %3;" : "=l"(d) : "l"(a), "l"(b), "l"(c));
    return d;
}
__device__ __forceinline__ float hsum2(u64 a) {
    float2 f;
    asm("mov.b64 {%0, %1}, %2;" : "=f"(f.x), "=f"(f.y) : "l"(a));
    return f.x + f.y;
}

#define DOT(re, ip, in, hl, hh, vl, vh)            \
    re = ffma2((hl).x, (vl).x, re);                \
    re = ffma2((hl).y, (vl).y, re);                \
    re = ffma2((hh).x, (vh).x, re);                \
    re = ffma2((hh).y, (vh).y, re);                \
    ip = ffma2((hh).x, (vl).x, ip);                \
    ip = ffma2((hh).y, (vl).y, ip);                \
    in = ffma2((hl).x, (vh).x, in);                \
    in = ffma2((hl).y, (vh).y, in);

// prefetch one batch's h,v tiles into this warp's smem slot (16B/lane/row)
__device__ __forceinline__ void prefetch_tiles(const float* __restrict__ hg,
                                               const float* __restrict__ vg,
                                               int b, int lane,
                                               unsigned sHa, unsigned sVa)
{
    const int lo = lane << 2;
    #pragma unroll
    for (int u = 0; u < NUSER; u++) {
        const int base = ((u * BATCH + b) << 7) + lo;
        asm volatile("cp.async.cg.shared.global [%0], [%1], 16;"
                     :: "r"(sHa + (unsigned)((u * ROWF + lo) * 4)), "l"(hg + base));
        asm volatile("cp.async.cg.shared.global [%0], [%1], 16;"
                     :: "r"(sVa + (unsigned)((u * ROWF + lo) * 4)), "l"(vg + base));
    }
    asm volatile("cp.async.commit_group;");
}

__global__ __launch_bounds__(THREADS, 8)
void se_fused_kernel(const float* __restrict__ hg,
                     const float* __restrict__ vg,
                     const float* __restrict__ Np,
                     float* __restrict__ out, int out_size)
{
    __shared__ __align__(16) float sh[WPB * WARP_TILE];
    __shared__ double sAcc[9];
    __shared__ int sLast;

    const int tid  = threadIdx.x;
    const int lane = tid & 31;
    const int wid  = tid >> 5;

    if (tid < 9) sAcc[tid] = 0.0;
    __syncthreads();

    const int gw = blockIdx.x * WPB + wid;
    const int nw = GRID * WPB;

    float* sH = sh + wid * WARP_TILE;
    float* sV = sH + TILE;
    const unsigned sHa = (unsigned)__cvta_generic_to_shared(sH);
    const unsigned sVa = (unsigned)__cvta_generic_to_shared(sV);

    const float Nval = __ldg(Np);

    // lane decomposition: c = col pair, a = row pair, k2 = t-split
    const int c  = lane & 3;
    const int a  = (lane >> 2) & 3;
    const int k2 = lane >> 4;

    const float* hr0 = sH + (2 * a) * ROWF;
    const float* hr1 = hr0 + ROWF;
    const float* vc0 = sV + (2 * c) * ROWF;
    const float* vc1 = vc0 + ROWF;
    const int t0 = k2 * 4;

    float accRp = 0.0f, accR0 = 0.0f, accR1 = 0.0f;

    prefetch_tiles(hg, vg, gw, lane, sHa, sVa);   // gw < BATCH always

    for (int b = gw; b < BATCH; ) {
        asm volatile("cp.async.wait_group 0;" ::: "memory");
        __syncwarp();

        // ---- ||v||^2 partial: read back this lane's staged slice ----
        u64 nrm2 = 0ULL;
        #pragma unroll
        for (int u = 0; u < NUSER; u++) {
            const ulonglong2 vv = *(const ulonglong2*)(sV + u * ROWF + (lane << 2));
            nrm2 = ffma2(vv.x, vv.x, nrm2);
            nrm2 = ffma2(vv.y, vv.y, nrm2);
        }

        // ---- 2x2 block of complex dots over this lane's t-half ----
        u64 re00 = 0, ip00 = 0, in00 = 0;
        u64 re01 = 0, ip01 = 0, in01 = 0;
        u64 re10 = 0, ip10 = 0, in10 = 0;
        u64 re11 = 0, ip11 = 0, in11 = 0;

        #pragma unroll
        for (int m = 0; m < 8; m++) {
            const int off = t0 + m * 8;
            const ulonglong2 h0l = *(const ulonglong2*)(hr0 + off);
            const ulonglong2 h0h = *(const ulonglong2*)(hr0 + off + 64);
            const ulonglong2 h1l = *(const ulonglong2*)(hr1 + off);
            const ulonglong2 h1h = *(const ulonglong2*)(hr1 + off + 64);
            const ulonglong2 v0l = *(const ulonglong2*)(vc0 + off);
            const ulonglong2 v0h = *(const ulonglong2*)(vc0 + off + 64);
            const ulonglong2 v1l = *(const ulonglong2*)(vc1 + off);
            const ulonglong2 v1h = *(const ulonglong2*)(vc1 + off + 64);

            DOT(re00, ip00, in00, h0l, h0h, v0l, v0h)
            DOT(re01, ip01, in01, h0l, h0h, v1l, v1h)
            DOT(re10, ip10, in10, h1l, h1h, v0l, v0h)
            DOT(re11, ip11, in11, h1l, h1h, v1l, v1h)
        }

        __syncwarp();           // all lanes done reading smem
        const int bn = b + nw;
        if (bn < BATCH)
            prefetch_tiles(hg, vg, bn, lane, sHa, sVa);   // overlaps below

        // ---- reductions (registers/shuffles only, smem free to refill) ----
        float nrm = hsum2(nrm2);
        #pragma unroll
        for (int o = 16; o; o >>= 1)
            nrm += __shfl_xor_sync(0xffffffffu, nrm, o);

        float Ar00 = hsum2(re00), Ai00 = hsum2(ip00) - hsum2(in00);
        float Ar01 = hsum2(re01), Ai01 = hsum2(ip01) - hsum2(in01);
        float Ar10 = hsum2(re10), Ai10 = hsum2(ip10) - hsum2(in10);
        float Ar11 = hsum2(re11), Ai11 = hsum2(ip11) - hsum2(in11);

        Ar00 += __shfl_xor_sync(0xffffffffu, Ar00, 16);
        Ai00 += __shfl_xor_sync(0xffffffffu, Ai00, 16);
        Ar01 += __shfl_xor_sync(0xffffffffu, Ar01, 16);
        Ai01 += __shfl_xor_sync(0xffffffffu, Ai01, 16);
        Ar10 += __shfl_xor_sync(0xffffffffu, Ar10, 16);
        Ai10 += __shfl_xor_sync(0xffffffffu, Ai10, 16);
        Ar11 += __shfl_xor_sync(0xffffffffu, Ar11, 16);
        Ai11 += __shfl_xor_sync(0xffffffffu, Ai11, 16);

        const float p00 = fmaf(Ar00, Ar00, Ai00 * Ai00);
        const float p01 = fmaf(Ar01, Ar01, Ai01 * Ai01);
        const float p10 = fmaf(Ar10, Ar10, Ai10 * Ai10);
        const float p11 = fmaf(Ar11, Ar11, Ai11 * Ai11);

        const float d0 = p00, d1 = p11;   // valid on lanes c==a

        float s0 = p00 + p01;
        float s1 = p10 + p11;
        s0 += __shfl_xor_sync(0xffffffffu, s0, 1);
        s1 += __shfl_xor_sync(0xffffffffu, s1, 1);
        s0 += __shfl_xor_sync(0xffffffffu, s0, 2);
        s1 += __shfl_xor_sync(0xffffffffu, s1, 2);

        if (c == a && k2 == 0) {
            const float scale2 = 8.0f / nrm;
            const float sinr0 = __fdividef(d0 * scale2, s0 - d0 + Nval);
            const float sinr1 = __fdividef(d1 * scale2, s1 - d1 + Nval);
            const float R0 = __log2f(1.0f + sinr0);
            const float R1 = __log2f(1.0f + sinr1);
            accR0 += R0;
            accR1 += R1;
            accRp += __exp10f(0.3f - R0) - R0
                   + __exp10f(0.3f - R1) - R1;
        }
        b = bn;
    }

    // ---- block-level reduction ----
    if (c == a && k2 == 0) {
        atomicAdd(&sAcc[0],         (double)accRp);
        atomicAdd(&sAcc[1 + 2 * a], (double)accR0);
        atomicAdd(&sAcc[2 + 2 * a], (double)accR1);
    }
    __syncthreads();

    if (tid < 9) atomicAdd(&gAcc[tid], sAcc[tid]);
    __threadfence();
    __syncthreads();

    if (tid == 0) {
        const unsigned old = atomicInc(&gCount, GRID - 1);
        sLast = (old == GRID - 1) ? 1 : 0;
    }
    __syncthreads();

    if (sLast && tid == 0) {
        __threadfence();
        const double inv = 1.0 / (double)BATCH;
        double r[9];
        #pragma unroll
        for (int i = 0; i < 9; i++) {
            r[i] = __ldcg(&gAcc[i]);
            __stcg(&gAcc[i], 0.0);
        }
        double s = 0.0;
        #pragma unroll
        for (int i = 1; i < 9; i++) s += r[i] * inv;
        if (out_size >= 1) out[0] = (float)(r[0] * inv);
        if (out_size >= 10) {
            #pragma unroll
            for (int i = 0; i < 8; i++) out[1 + i] = (float)(r[1 + i] * inv);
            out[9] = (float)s;
        }
    }
}

extern "C" void kernel_launch(void* const* d_in, const int* in_sizes, int n_in,
                              void* d_out, int out_size)
{
    const float* h = (const float*)d_in[0];
    const float* v = (const float*)d_in[1];
    const float* N = (const float*)d_in[2];
    float* out = (float*)d_out;

    se_fused_kernel<<<GRID, THREADS>>>(h, v, N, out, out_size);
}

// round 6
// speedup vs baseline: 2.1057x; 1.1717x over previous
#include <cuda_runtime.h>

// SE_loss_w_threshold: h,v (8,16384,128) fp32, N scalar.
// out (10 fp32): [mean_Rp, R_per_user[0..7], sum(R_per_user)]
// R6: per-warp DOUBLE-buffered cp.async pipeline (wait_group 1) -> DRAM
// latency fully hidden after fill. Dynamic smem 67.6KB, 3 blocks/SM, GRID=444.

#define NUSER 8
#define BATCH 16384
#define ROWF  132                      // padded row stride (floats), conflict-free
#define TILE  (NUSER * ROWF)
#define WARP_TILE (2 * TILE)           // h tile + v tile (floats)
#define WPB   4
#define THREADS (WPB * 32)
#define GRID  444                      // 148 SMs * 3 blocks/SM, single wave
#define BUF_STRIDE_B (WPB * WARP_TILE * 4)        // bytes between buffers
#define SMEM_BYTES   (2 * WPB * WARP_TILE * 4)    // two buffers

typedef unsigned long long u64;

__device__ double gAcc[9];
__device__ unsigned int gCount = 0;

__device__ __forceinline__ u64 ffma2(u64 a, u64 b, u64 c) {
    u64 d;
    asm("fma.rn.f32x2 %0, %1, %2, %3;" : "=l"(d) : "l"(a), "l"(b), "l"(c));
    return d;
}
__device__ __forceinline__ float hsum2(u64 a) {
    float2 f;
    asm("mov.b64 {%0, %1}, %2;" : "=f"(f.x), "=f"(f.y) : "l"(a));
    return f.x + f.y;
}

#define DOT(re, ip, in, hl, hh, vl, vh)            \
    re = ffma2((hl).x, (vl).x, re);                \
    re = ffma2((hl).y, (vl).y, re);                \
    re = ffma2((hh).x, (vh).x, re);                \
    re = ffma2((hh).y, (vh).y, re);                \
    ip = ffma2((hh).x, (vl).x, ip);                \
    ip = ffma2((hh).y, (vl).y, ip);                \
    in = ffma2((hl).x, (vh).x, in);                \
    in = ffma2((hl).y, (vh).y, in);

// stage one batch's h,v tiles into the given smem buffer (16B/lane/row)
__device__ __forceinline__ void prefetch_tiles(const float* __restrict__ hg,
                                               const float* __restrict__ vg,
                                               int b, int lane, unsigned bufa)
{
    const int lo = lane << 2;
    const unsigned sHa = bufa + (unsigned)(lo * 4);
    const unsigned sVa = sHa + (unsigned)(TILE * 4);
    #pragma unroll
    for (int u = 0; u < NUSER; u++) {
        const int base = ((u * BATCH + b) << 7) + lo;
        asm volatile("cp.async.cg.shared.global [%0], [%1], 16;"
                     :: "r"(sHa + (unsigned)(u * ROWF * 4)), "l"(hg + base));
        asm volatile("cp.async.cg.shared.global [%0], [%1], 16;"
                     :: "r"(sVa + (unsigned)(u * ROWF * 4)), "l"(vg + base));
    }
}

__global__ __launch_bounds__(THREADS)
void se_fused_kernel(const float* __restrict__ hg,
                     const float* __restrict__ vg,
                     const float* __restrict__ Np,
                     float* __restrict__ out, int out_size)
{
    extern __shared__ __align__(16) float sh[];
    __shared__ double sAcc[9];
    __shared__ int sLast;

    const int tid  = threadIdx.x;
    const int lane = tid & 31;
    const int wid  = tid >> 5;

    if (tid < 9) sAcc[tid] = 0.0;
    __syncthreads();

    const int gw = blockIdx.x * WPB + wid;
    const int nw = GRID * WPB;

    float* myBase = sh + wid * WARP_TILE;                 // buffer 0
    const unsigned base0 = (unsigned)__cvta_generic_to_shared(myBase);

    const float Nval = __ldg(Np);

    // lane decomposition: c = col pair, a = row pair, k2 = t-split
    const int c  = lane & 3;
    const int a  = (lane >> 2) & 3;
    const int k2 = lane >> 4;
    const int t0 = k2 * 4;

    float accRp = 0.0f, accR0 = 0.0f, accR1 = 0.0f;

    // pipeline fill: two batches in flight (every warp has >= 2 batches)
    prefetch_tiles(hg, vg, gw, lane, base0);
    asm volatile("cp.async.commit_group;");
    prefetch_tiles(hg, vg, gw + nw, lane, base0 + BUF_STRIDE_B);
    asm volatile("cp.async.commit_group;");

    int buf = 0;
    for (int b = gw; b < BATCH; b += nw, buf ^= 1) {
        asm volatile("cp.async.wait_group 1;" ::: "memory");
        __syncwarp();

        float* sHb = sh + (buf * WPB + wid) * WARP_TILE;
        float* sVb = sHb + TILE;
        const float* hr0 = sHb + (2 * a) * ROWF;
        const float* hr1 = hr0 + ROWF;
        const float* vc0 = sVb + (2 * c) * ROWF;
        const float* vc1 = vc0 + ROWF;

        // ---- ||v||^2 partial (reduced later, off critical path) ----
        u64 nrm2 = 0ULL;
        #pragma unroll
        for (int u = 0; u < NUSER; u++) {
            const ulonglong2 vv = *(const ulonglong2*)(sVb + u * ROWF + (lane << 2));
            nrm2 = ffma2(vv.x, vv.x, nrm2);
            nrm2 = ffma2(vv.y, vv.y, nrm2);
        }

        // ---- 2x2 block of complex dots over this lane's t-half ----
        u64 re00 = 0, ip00 = 0, in00 = 0;
        u64 re01 = 0, ip01 = 0, in01 = 0;
        u64 re10 = 0, ip10 = 0, in10 = 0;
        u64 re11 = 0, ip11 = 0, in11 = 0;

        #pragma unroll
        for (int m = 0; m < 8; m++) {
            const int off = t0 + m * 8;
            const ulonglong2 h0l = *(const ulonglong2*)(hr0 + off);
            const ulonglong2 h0h = *(const ulonglong2*)(hr0 + off + 64);
            const ulonglong2 h1l = *(const ulonglong2*)(hr1 + off);
            const ulonglong2 h1h = *(const ulonglong2*)(hr1 + off + 64);
            const ulonglong2 v0l = *(const ulonglong2*)(vc0 + off);
            const ulonglong2 v0h = *(const ulonglong2*)(vc0 + off + 64);
            const ulonglong2 v1l = *(const ulonglong2*)(vc1 + off);
            const ulonglong2 v1h = *(const ulonglong2*)(vc1 + off + 64);

            DOT(re00, ip00, in00, h0l, h0h, v0l, v0h)
            DOT(re01, ip01, in01, h0l, h0h, v1l, v1h)
            DOT(re10, ip10, in10, h1l, h1h, v0l, v0h)
            DOT(re11, ip11, in11, h1l, h1h, v1l, v1h)
        }

        __syncwarp();                       // all lanes done reading this buffer
        const int bp = b + 2 * nw;          // refill the buffer just consumed
        if (bp < BATCH)
            prefetch_tiles(hg, vg, bp, lane, base0 + (unsigned)buf * BUF_STRIDE_B);
        asm volatile("cp.async.commit_group;");   // always commit (may be empty)

        // ---- reductions (registers/shuffles only) ----
        float nrm = hsum2(nrm2);
        #pragma unroll
        for (int o = 16; o; o >>= 1)
            nrm += __shfl_xor_sync(0xffffffffu, nrm, o);

        float Ar00 = hsum2(re00), Ai00 = hsum2(ip00) - hsum2(in00);
        float Ar01 = hsum2(re01), Ai01 = hsum2(ip01) - hsum2(in01);
        float Ar10 = hsum2(re10), Ai10 = hsum2(ip10) - hsum2(in10);
        float Ar11 = hsum2(re11), Ai11 = hsum2(ip11) - hsum2(in11);

        Ar00 += __shfl_xor_sync(0xffffffffu, Ar00, 16);
        Ai00 += __shfl_xor_sync(0xffffffffu, Ai00, 16);
        Ar01 += __shfl_xor_sync(0xffffffffu, Ar01, 16);
        Ai01 += __shfl_xor_sync(0xffffffffu, Ai01, 16);
        Ar10 += __shfl_xor_sync(0xffffffffu, Ar10, 16);
        Ai10 += __shfl_xor_sync(0xffffffffu, Ai10, 16);
        Ar11 += __shfl_xor_sync(0xffffffffu, Ar11, 16);
        Ai11 += __shfl_xor_sync(0xffffffffu, Ai11, 16);

        const float p00 = fmaf(Ar00, Ar00, Ai00 * Ai00);
        const float p01 = fmaf(Ar01, Ar01, Ai01 * Ai01);
        const float p10 = fmaf(Ar10, Ar10, Ai10 * Ai10);
        const float p11 = fmaf(Ar11, Ar11, Ai11 * Ai11);

        const float d0 = p00, d1 = p11;     // valid on lanes c==a

        float s0 = p00 + p01;
        float s1 = p10 + p11;
        s0 += __shfl_xor_sync(0xffffffffu, s0, 1);
        s1 += __shfl_xor_sync(0xffffffffu, s1, 1);
        s0 += __shfl_xor_sync(0xffffffffu, s0, 2);
        s1 += __shfl_xor_sync(0xffffffffu, s1, 2);

        if (c == a && k2 == 0) {
            const float scale2 = 8.0f / nrm;
            const float sinr0 = __fdividef(d0 * scale2, s0 - d0 + Nval);
            const float sinr1 = __fdividef(d1 * scale2, s1 - d1 + Nval);
            const float R0 = __log2f(1.0f + sinr0);
            const float R1 = __log2f(1.0f + sinr1);
            accR0 += R0;
            accR1 += R1;
            accRp += __exp10f(0.3f - R0) - R0
                   + __exp10f(0.3f - R1) - R1;
        }
    }

    // ---- block-level reduction ----
    if (c == a && k2 == 0) {
        atomicAdd(&sAcc[0],         (double)accRp);
        atomicAdd(&sAcc[1 + 2 * a], (double)accR0);
        atomicAdd(&sAcc[2 + 2 * a], (double)accR1);
    }
    __syncthreads();

    if (tid < 9) atomicAdd(&gAcc[tid], sAcc[tid]);
    __threadfence();
    __syncthreads();

    if (tid == 0) {
        const unsigned old = atomicInc(&gCount, GRID - 1);
        sLast = (old == GRID - 1) ? 1 : 0;
    }
    __syncthreads();

    if (sLast && tid == 0) {
        __threadfence();
        const double inv = 1.0 / (double)BATCH;
        double r[9];
        #pragma unroll
        for (int i = 0; i < 9; i++) {
            r[i] = __ldcg(&gAcc[i]);
            __stcg(&gAcc[i], 0.0);
        }
        double s = 0.0;
        #pragma unroll
        for (int i = 1; i < 9; i++) s += r[i] * inv;
        if (out_size >= 1) out[0] = (float)(r[0] * inv);
        if (out_size >= 10) {
            #pragma unroll
            for (int i = 0; i < 8; i++) out[1 + i] = (float)(r[1 + i] * inv);
            out[9] = (float)s;
        }
    }
}

extern "C" void kernel_launch(void* const* d_in, const int* in_sizes, int n_in,
                              void* d_out, int out_size)
{
    const float* h = (const float*)d_in[0];
    const float* v = (const float*)d_in[1];
    const float* N = (const float*)d_in[2];
    float* out = (float*)d_out;

    cudaFuncSetAttribute(se_fused_kernel,
                         cudaFuncAttributeMaxDynamicSharedMemorySize, SMEM_BYTES);
    se_fused_kernel<<<GRID, THREADS, SMEM_BYTES>>>(h, v, N, out, out_size);
}